// round 16
// baseline (speedup 1.0000x reference)
#include <cuda_runtime.h>
#include <cstdint>

#define BB 8
#define DD 64
#define KK 32
#define HW 3136          // 56*56
#define HALF2 (HW/4)     // 784 float2's per half-row
#define NBLK (BB*DD*2)   // 1024 main CTAs
#define LOG2E 1.4426950408889634f

// Scratch (allocation-free rule: __device__ globals)
__device__ float g_EMp[NBLK];        // per-half-row partial sums of E
__device__ float g_gp1[BB * DD];     // 1 + gamma
__device__ unsigned int g_cnt;       // zero at load; last CTA resets each run

__device__ __forceinline__ float fast_ex2(float x) {
    float y; asm("ex2.approx.ftz.f32 %0, %1;" : "=f"(y) : "f"(x)); return y;
}
__device__ __forceinline__ float fast_rcp(float x) {
    float y; asm("rcp.approx.ftz.f32 %0, %1;" : "=f"(y) : "f"(x)); return y;
}

// ───────────────────────── Kernel 1: main (+ gamma tail) ─────────────────────────
// 1024 CTAs × 128 thr; CTA (bd, half) computes E[b,d,n] over half a row using
// packed f32x2 math: e_k = exp2(A x² + B x + C), E = x - (Σ e_k c_k)/(Σ e_k).
// scale ≤ 0 ⇒ logits ≤ 0 ⇒ single-pass softmax safe.
// Constants re-fetched per n-iter via asm-volatile LDS (anti-hoist: R11/R12
// showed ptxas otherwise burns 128 regs and collapses occupancy).
// The LAST CTA (atomic ticket) computes all 512 gammas into g_gp1.
__global__ __launch_bounds__(128) void enc_main_kernel(
    const float* __restrict__ X,
    const float* __restrict__ codewords,
    const float* __restrict__ scale,
    const float* __restrict__ fc_w,
    const float* __restrict__ fc_b,
    float* __restrict__ outE)
{
    __shared__ float kc2[KK * 8];     // per k: A,A,B,B,C,C,c,c
    const int blk  = blockIdx.x;
    const int bd   = blk >> 1;
    const int half = blk & 1;
    const int d    = bd & (DD - 1);

    if (threadIdx.x < KK) {
        const int k = threadIdx.x;
        float c  = codewords[k * DD + d];
        float st = scale[k * DD + d] * LOG2E;
        float B  = -2.0f * st * c;
        float C  = st * c * c;
        float* p = kc2 + k * 8;
        p[0] = st; p[1] = st;
        p[2] = B;  p[3] = B;
        p[4] = C;  p[5] = C;
        p[6] = c;  p[7] = c;
    }
    __syncthreads();

    const uint32_t kc_base = (uint32_t)__cvta_generic_to_shared(kc2);
    const float2* __restrict__ xp2 = (const float2*)(X    + (size_t)bd * HW) + half * HALF2;
    float2* __restrict__       ep2 = (float2*)      (outE + (size_t)bd * HW) + half * HALF2;

    float local = 0.0f;
    for (int i = threadIdx.x; i < HALF2; i += 128) {
        const float2 xv = xp2[i];
        uint64_t x01, q01, den, cm;
        asm("mov.b64 %0, {%1,%2};" : "=l"(x01) : "f"(xv.x), "f"(xv.y));
        asm("mul.rn.f32x2 %0, %1, %1;" : "=l"(q01) : "l"(x01));
        asm("mov.b64 %0, {%1,%2};" : "=l"(den) : "f"(0.0f), "f"(0.0f));
        cm = den;
#pragma unroll
        for (int k = 0; k < KK; k++) {
            uint64_t AA, BBp, CC, cc;
            asm volatile("ld.shared.v2.u64 {%0,%1}, [%2];"
                         : "=l"(AA), "=l"(BBp) : "r"(kc_base + k * 32));
            asm volatile("ld.shared.v2.u64 {%0,%1}, [%2];"
                         : "=l"(CC), "=l"(cc) : "r"(kc_base + k * 32 + 16));
            uint64_t w, v;
            asm("fma.rn.f32x2 %0, %1, %2, %3;" : "=l"(w) : "l"(BBp), "l"(x01), "l"(CC));
            asm("fma.rn.f32x2 %0, %1, %2, %3;" : "=l"(v) : "l"(AA),  "l"(q01), "l"(w));
            float v0, v1;
            asm("mov.b64 {%0,%1}, %2;" : "=f"(v0), "=f"(v1) : "l"(v));
            float e0 = fast_ex2(v0);
            float e1 = fast_ex2(v1);
            uint64_t e01;
            asm("mov.b64 %0, {%1,%2};" : "=l"(e01) : "f"(e0), "f"(e1));
            asm("add.rn.f32x2 %0, %1, %2;"     : "=l"(den) : "l"(den), "l"(e01));
            asm("fma.rn.f32x2 %0, %1, %2, %3;" : "=l"(cm)  : "l"(e01), "l"(cc), "l"(cm));
        }
        float den0, den1, cm0, cm1;
        asm("mov.b64 {%0,%1}, %2;" : "=f"(den0), "=f"(den1) : "l"(den));
        asm("mov.b64 {%0,%1}, %2;" : "=f"(cm0),  "=f"(cm1)  : "l"(cm));
        float2 ev;
        ev.x = fmaf(-cm0, fast_rcp(den0), xv.x);
        ev.y = fmaf(-cm1, fast_rcp(den1), xv.y);
        ep2[i] = ev;
        local += ev.x + ev.y;
    }

    // CTA-reduce EM partial, publish, take a ticket
    const int lane = threadIdx.x & 31, warp = threadIdx.x >> 5;
#pragma unroll
    for (int off = 16; off > 0; off >>= 1)
        local += __shfl_xor_sync(0xffffffff, local, off);
    __shared__ float red[4];
    __shared__ int s_last;
    if (lane == 0) red[warp] = local;
    __syncthreads();
    if (threadIdx.x == 0) {
        g_EMp[blk] = red[0] + red[1] + red[2] + red[3];
        __threadfence();
        unsigned int t = atomicAdd(&g_cnt, 1u);
        s_last = (t == NBLK - 1u);
    }
    __syncthreads();
    if (!s_last) return;

    // ── Last CTA: compute all 512 gammas ──
    __shared__ float sEM[BB * DD];
    __shared__ float sW[DD * 65];                 // padded rows
    for (int i = threadIdx.x; i < BB * DD; i += 128)
        sEM[i] = (g_EMp[2 * i] + g_EMp[2 * i + 1]) * (1.0f / (float)KK);
    for (int i = threadIdx.x; i < DD * DD; i += 128)
        sW[(i >> 6) * 65 + (i & 63)] = fc_w[i];
    __syncthreads();

    for (int g = threadIdx.x; g < BB * DD; g += 128) {
        const int b = g >> 6, dd = g & 63;
        float a0 = fc_b[dd], a1 = 0.f, a2 = 0.f, a3 = 0.f;
#pragma unroll
        for (int j = 0; j < DD; j += 4) {
            a0 = fmaf(sEM[b * DD + j + 0], sW[dd * 65 + j + 0], a0);
            a1 = fmaf(sEM[b * DD + j + 1], sW[dd * 65 + j + 1], a1);
            a2 = fmaf(sEM[b * DD + j + 2], sW[dd * 65 + j + 2], a2);
            a3 = fmaf(sEM[b * DD + j + 3], sW[dd * 65 + j + 3], a3);
        }
        float acc = (a0 + a1) + (a2 + a3);
        g_gp1[g] = 1.0f + fast_rcp(1.0f + fast_ex2(-acc * LOG2E));
    }
    if (threadIdx.x == 0) g_cnt = 0;              // reset for next replay
}

// ───────────────────────── Kernel 2: scale+relu ─────────────────────────
// Pure loop-free streaming: 3136 CTAs × 128 threads, one float4 per thread,
// no smem, no barriers. E is L2-resident from kernel 1.
__global__ __launch_bounds__(128) void enc_scale_kernel(float* __restrict__ out)
{
    const int idx = blockIdx.x * 128 + threadIdx.x;   // float4 index
    const int bd  = idx / (HW / 4);                   // 784 float4's per row
    const float gm = g_gp1[bd];

    float4* __restrict__ p = (float4*)out;
    float4 v = p[idx];
    v.x = fmaxf(v.x * gm, 0.0f);
    v.y = fmaxf(v.y * gm, 0.0f);
    v.z = fmaxf(v.z * gm, 0.0f);
    v.w = fmaxf(v.w * gm, 0.0f);
    p[idx] = v;
}

extern "C" void kernel_launch(void* const* d_in, const int* in_sizes, int n_in,
                              void* d_out, int out_size) {
    const float* X    = (const float*)d_in[0];
    const float* cw   = (const float*)d_in[1];
    const float* sc   = (const float*)d_in[2];
    const float* fc_w = (const float*)d_in[3];
    const float* fc_b = (const float*)d_in[4];
    float* out = (float*)d_out;

    enc_main_kernel <<<NBLK, 128>>>(X, cw, sc, fc_w, fc_b, out);
    enc_scale_kernel<<<(BB * DD * HW) / (4 * 128), 128>>>(out);
}

// round 17
// speedup vs baseline: 1.1503x; 1.1503x over previous
#include <cuda_runtime.h>
#include <cstdint>

#define BB 8
#define DD 64
#define KK 32
#define HW 3136          // 56*56
#define LOG2E 1.4426950408889634f

// Scratch (allocation-free rule: __device__ globals, rewritten every replay)
__device__ float g_EM[BB * DD];     // EM[b,d] (pre-divided by K)
__device__ float g_gp1[BB * DD];    // 1 + gamma

__device__ __forceinline__ float fast_ex2(float x) {
    float y; asm("ex2.approx.ftz.f32 %0, %1;" : "=f"(y) : "f"(x)); return y;
}
__device__ __forceinline__ float fast_rcp(float x) {
    float y; asm("rcp.approx.ftz.f32 %0, %1;" : "=f"(y) : "f"(x)); return y;
}

// ───────────────────────── Kernel 1: main (R14 config, proven 15.7 µs) ─────────────────
// One CTA per (b,d) row, 256 threads, 2 n-values per thread-iter packed into
// f32x2 lanes. E[n] = x - (Σ_k e_k c_k)/(Σ_k e_k), e_k = exp2(A x² + B x + C).
// scale ≤ 0 ⇒ logits ≤ 0 ⇒ single-pass softmax safe.
// Constants duplicated in smem, re-fetched per n-iter via asm-volatile LDS
// (anti-hoist: otherwise ptxas burns 128 regs and occupancy collapses).
__global__ __launch_bounds__(256) void enc_main_kernel(
    const float* __restrict__ X,
    const float* __restrict__ codewords,
    const float* __restrict__ scale,
    float* __restrict__ outE)
{
    __shared__ float kc2[KK * 8];     // per k: A,A,B,B,C,C,c,c  (32 B)
    const int bd = blockIdx.x;
    const int d  = bd & (DD - 1);

    if (threadIdx.x < KK) {
        const int k = threadIdx.x;
        float c  = codewords[k * DD + d];
        float st = scale[k * DD + d] * LOG2E;
        float B  = -2.0f * st * c;
        float C  = st * c * c;
        float* p = kc2 + k * 8;
        p[0] = st; p[1] = st;
        p[2] = B;  p[3] = B;
        p[4] = C;  p[5] = C;
        p[6] = c;  p[7] = c;
    }
    __syncthreads();

    const uint32_t kc_base = (uint32_t)__cvta_generic_to_shared(kc2);

    const float2* __restrict__ xp2 = (const float2*)(X    + (size_t)bd * HW);
    float2* __restrict__       ep2 = (float2*)      (outE + (size_t)bd * HW);

    float local = 0.0f;
    for (int i = threadIdx.x; i < HW / 2; i += 256) {   // 1568 float2's
        const float2 xv = xp2[i];
        uint64_t x01, q01, den, cm;
        asm("mov.b64 %0, {%1,%2};" : "=l"(x01) : "f"(xv.x), "f"(xv.y));
        asm("mul.rn.f32x2 %0, %1, %1;" : "=l"(q01) : "l"(x01));
        asm("mov.b64 %0, {%1,%2};" : "=l"(den) : "f"(0.0f), "f"(0.0f));
        cm = den;
#pragma unroll
        for (int k = 0; k < KK; k++) {
            uint64_t AA, BBp, CC, cc;
            asm volatile("ld.shared.v2.u64 {%0,%1}, [%2];"
                         : "=l"(AA), "=l"(BBp) : "r"(kc_base + k * 32));
            asm volatile("ld.shared.v2.u64 {%0,%1}, [%2];"
                         : "=l"(CC), "=l"(cc) : "r"(kc_base + k * 32 + 16));
            uint64_t w, v;
            asm("fma.rn.f32x2 %0, %1, %2, %3;" : "=l"(w) : "l"(BBp), "l"(x01), "l"(CC));
            asm("fma.rn.f32x2 %0, %1, %2, %3;" : "=l"(v) : "l"(AA),  "l"(q01), "l"(w));
            float v0, v1;
            asm("mov.b64 {%0,%1}, %2;" : "=f"(v0), "=f"(v1) : "l"(v));
            float e0 = fast_ex2(v0);
            float e1 = fast_ex2(v1);
            uint64_t e01;
            asm("mov.b64 %0, {%1,%2};" : "=l"(e01) : "f"(e0), "f"(e1));
            asm("add.rn.f32x2 %0, %1, %2;"      : "=l"(den) : "l"(den), "l"(e01));
            asm("fma.rn.f32x2 %0, %1, %2, %3;"  : "=l"(cm)  : "l"(e01), "l"(cc), "l"(cm));
        }
        float den0, den1, cm0, cm1;
        asm("mov.b64 {%0,%1}, %2;" : "=f"(den0), "=f"(den1) : "l"(den));
        asm("mov.b64 {%0,%1}, %2;" : "=f"(cm0),  "=f"(cm1)  : "l"(cm));
        float2 ev;
        ev.x = fmaf(-cm0, fast_rcp(den0), xv.x);
        ev.y = fmaf(-cm1, fast_rcp(den1), xv.y);
        ep2[i] = ev;
        local += ev.x + ev.y;
    }

    // Reduce EM partial across the CTA
    const int lane = threadIdx.x & 31, warp = threadIdx.x >> 5;
#pragma unroll
    for (int off = 16; off > 0; off >>= 1)
        local += __shfl_xor_sync(0xffffffff, local, off);
    __shared__ float red[8];
    if (lane == 0) red[warp] = local;
    __syncthreads();
    if (threadIdx.x == 0) {
        float s = 0.f;
#pragma unroll
        for (int w = 0; w < 8; w++) s += red[w];
        g_EM[bd] = s * (1.0f / (float)KK);
    }
}

// ───────────────────────── Kernel 2: gamma ─────────────────────────
// One block, 512 threads: thread t=(b,d) → g_gp1[t] = 1 + sigmoid(EM[b,:]·fc_w[d,:] + fc_b[d])
__global__ __launch_bounds__(512) void enc_gamma_kernel(
    const float* __restrict__ fc_w,
    const float* __restrict__ fc_b)
{
    __shared__ float sEM[BB * DD];
    __shared__ float sW[DD * 65];          // padded rows: no bank conflicts
    const int t = threadIdx.x;

    sEM[t] = g_EM[t];
#pragma unroll
    for (int i = 0; i < 8; i++) {
        int idx = t + i * 512;
        sW[(idx >> 6) * 65 + (idx & 63)] = fc_w[idx];
    }
    __syncthreads();

    const int b = t >> 6, d = t & 63;
    float a0 = fc_b[d], a1 = 0.f, a2 = 0.f, a3 = 0.f;
#pragma unroll
    for (int j = 0; j < DD; j += 4) {
        a0 = fmaf(sEM[b * DD + j + 0], sW[d * 65 + j + 0], a0);
        a1 = fmaf(sEM[b * DD + j + 1], sW[d * 65 + j + 1], a1);
        a2 = fmaf(sEM[b * DD + j + 2], sW[d * 65 + j + 2], a2);
        a3 = fmaf(sEM[b * DD + j + 3], sW[d * 65 + j + 3], a3);
    }
    float acc = (a0 + a1) + (a2 + a3);
    g_gp1[t] = 1.0f + fast_rcp(1.0f + fast_ex2(-acc * LOG2E));   // 1 + sigmoid
}

// ───────────────────────── Kernel 3: scale+relu (MLP=4) ─────────────────────────
// 784 CTAs × 128 threads; each thread handles 4 float4's at stride 128 within a
// 512-float4 CTA tile. All 4 gm loads then all 4 data loads are issued
// back-to-back (MLP=4) before any dependent math — this is what was missing in
// the 5.9 µs / 11%-issue R15 version (MLP=1).
__global__ __launch_bounds__(128) void enc_scale_kernel(float* __restrict__ out)
{
    const int base = blockIdx.x * 512 + threadIdx.x;   // float4 index
    float4* __restrict__ p = (float4*)out;

    int   idx[4];
    float gm [4];
    float4 v [4];
#pragma unroll
    for (int j = 0; j < 4; j++) idx[j] = base + j * 128;
#pragma unroll
    for (int j = 0; j < 4; j++) gm[j] = g_gp1[idx[j] / (HW / 4)];  // broadcast-ish
#pragma unroll
    for (int j = 0; j < 4; j++) v[j] = p[idx[j]];
#pragma unroll
    for (int j = 0; j < 4; j++) {
        v[j].x = fmaxf(v[j].x * gm[j], 0.0f);
        v[j].y = fmaxf(v[j].y * gm[j], 0.0f);
        v[j].z = fmaxf(v[j].z * gm[j], 0.0f);
        v[j].w = fmaxf(v[j].w * gm[j], 0.0f);
        p[idx[j]] = v[j];
    }
}

extern "C" void kernel_launch(void* const* d_in, const int* in_sizes, int n_in,
                              void* d_out, int out_size) {
    const float* X    = (const float*)d_in[0];
    const float* cw   = (const float*)d_in[1];
    const float* sc   = (const float*)d_in[2];
    const float* fc_w = (const float*)d_in[3];
    const float* fc_b = (const float*)d_in[4];
    float* out = (float*)d_out;

    enc_main_kernel <<<BB * DD, 256>>>(X, cw, sc, out);
    enc_gamma_kernel<<<1, 512>>>(fc_w, fc_b);
    // total float4's = 8*64*3136/4 = 401408 = 784 CTAs * 512
    enc_scale_kernel<<<784, 128>>>(out);
}